// round 12
// baseline (speedup 1.0000x reference)
#include <cuda_runtime.h>

// out[t, :] = W[seq[t], :] + W[pre[t], :] + W[post[t], :]
// D = 128 floats (512B row); lane l -> float4 #l; warp covers a full row.
// Verdict: LTS(L2-crossbar)-byte bound. 268MB SM<->L2 per launch at the
// ~6300 B/cyc chip cap (~11.9 TB/s @NAT) == measured 22.5us. Bytes are
// irreducible for uniform-random gathers. Persistent single-wave grid;
// residency is REGISTER-limited (48 regs -> 5 CTAs/SM), so one wave =
// 148*5 = 740 blocks (R9's 592 left one CTA slot idle per SM).

#define EMBED_VEC 32
#define THREADS_PER_BLOCK 256
#define WARPS_PER_BLOCK (THREADS_PER_BLOCK / 32)
#define TPW 4                 // tokens per warp-chunk
#define GRID_BLOCKS 740       // 148 SMs * 5 resident CTAs (48-reg limit)

__global__ __launch_bounds__(THREADS_PER_BLOCK)
void cbow_subword_kernel(const int* __restrict__ seq,
                         const int* __restrict__ pre,
                         const int* __restrict__ post,
                         const float4* __restrict__ W,
                         float4* __restrict__ out,
                         int n_tok) {
    const int warp = blockIdx.x * WARPS_PER_BLOCK + (threadIdx.x >> 5);
    const int lane = threadIdx.x & 31;
    const int n_warps = gridDim.x * WARPS_PER_BLOCK;
    const long long chunk_stride = (long long)n_warps * TPW;

    for (long long t0 = (long long)warp * TPW; t0 < n_tok; t0 += chunk_stride) {
        if (t0 + TPW <= n_tok) {
            // 3 vectorized index broadcasts (t0 is 4-aligned).
            int4 s = __ldg((const int4*)(seq  + t0));
            int4 p = __ldg((const int4*)(pre  + t0));
            int4 q = __ldg((const int4*)(post + t0));
            int ia[TPW] = {s.x, s.y, s.z, s.w};
            int ib[TPW] = {p.x, p.y, p.z, p.w};
            int ic[TPW] = {q.x, q.y, q.z, q.w};

            // 12 independent gathers issued before first use (MLP=12).
            float4 va[TPW], vb[TPW], vc[TPW];
            #pragma unroll
            for (int j = 0; j < TPW; j++) va[j] = __ldg(W + (size_t)ia[j] * EMBED_VEC + lane);
            #pragma unroll
            for (int j = 0; j < TPW; j++) vb[j] = __ldg(W + (size_t)ib[j] * EMBED_VEC + lane);
            #pragma unroll
            for (int j = 0; j < TPW; j++) vc[j] = __ldg(W + (size_t)ic[j] * EMBED_VEC + lane);

            #pragma unroll
            for (int j = 0; j < TPW; j++) {
                float4 r;
                r.x = va[j].x + vb[j].x + vc[j].x;
                r.y = va[j].y + vb[j].y + vc[j].y;
                r.z = va[j].z + vb[j].z + vc[j].z;
                r.w = va[j].w + vb[j].w + vc[j].w;
                // Streaming store: keep the 51MB weight table L2-resident.
                __stcs(out + (size_t)(t0 + j) * EMBED_VEC + lane, r);
            }
        } else {
            for (long long t = t0; t < n_tok; t++) {
                int i0 = __ldg(seq + t), i1 = __ldg(pre + t), i2 = __ldg(post + t);
                float4 a = __ldg(W + (size_t)i0 * EMBED_VEC + lane);
                float4 b = __ldg(W + (size_t)i1 * EMBED_VEC + lane);
                float4 c = __ldg(W + (size_t)i2 * EMBED_VEC + lane);
                float4 r;
                r.x = a.x + b.x + c.x;
                r.y = a.y + b.y + c.y;
                r.z = a.z + b.z + c.z;
                r.w = a.w + b.w + c.w;
                __stcs(out + (size_t)t * EMBED_VEC + lane, r);
            }
        }
    }
}

extern "C" void kernel_launch(void* const* d_in, const int* in_sizes, int n_in,
                              void* d_out, int out_size) {
    const int*    seq  = (const int*)d_in[0];
    const int*    pre  = (const int*)d_in[1];
    const int*    post = (const int*)d_in[2];
    const float4* W    = (const float4*)d_in[3];
    float4*       out  = (float4*)d_out;

    int n_tok = in_sizes[0];  // 131072

    // Single-wave persistent grid; shrink for tiny inputs.
    int chunks = (n_tok + TPW - 1) / TPW;
    int blocks_needed = (chunks + WARPS_PER_BLOCK - 1) / WARPS_PER_BLOCK;
    int blocks = GRID_BLOCKS < blocks_needed ? GRID_BLOCKS : blocks_needed;
    if (blocks < 1) blocks = 1;

    cbow_subword_kernel<<<blocks, THREADS_PER_BLOCK>>>(seq, pre, post, W, out, n_tok);
}

// round 13
// speedup vs baseline: 1.0271x; 1.0271x over previous
#include <cuda_runtime.h>

// out[t, :] = W[seq[t], :] + W[pre[t], :] + W[post[t], :]
// D = 128 floats (512B row); lane l -> float4 #l; warp covers a full row.
// LTS(L2-crossbar)-byte bound: 268MB SM<->L2 per launch @ ~12.3 TB/s
// measured. Bytes irreducible. Persistent single-wave grid; force 40 regs
// (launch_bounds minBlocks=6) so residency rises to 6 CTAs/SM -> one wave
// = 148*6 = 888 blocks, ~70% occ, +20% in-flight gathers vs R12.

#define EMBED_VEC 32
#define THREADS_PER_BLOCK 256
#define WARPS_PER_BLOCK (THREADS_PER_BLOCK / 32)
#define TPW 4                 // tokens per warp-chunk
#define GRID_BLOCKS 888       // 148 SMs * 6 resident CTAs (40-reg budget)

__global__ __launch_bounds__(THREADS_PER_BLOCK, 6)
void cbow_subword_kernel(const int* __restrict__ seq,
                         const int* __restrict__ pre,
                         const int* __restrict__ post,
                         const float4* __restrict__ W,
                         float4* __restrict__ out,
                         int n_tok) {
    const int warp = blockIdx.x * WARPS_PER_BLOCK + (threadIdx.x >> 5);
    const int lane = threadIdx.x & 31;
    const int n_warps = gridDim.x * WARPS_PER_BLOCK;
    const long long chunk_stride = (long long)n_warps * TPW;

    for (long long t0 = (long long)warp * TPW; t0 < n_tok; t0 += chunk_stride) {
        if (t0 + TPW <= n_tok) {
            // 3 vectorized index broadcasts (t0 is 4-aligned).
            int4 s = __ldg((const int4*)(seq  + t0));
            int4 p = __ldg((const int4*)(pre  + t0));
            int4 q = __ldg((const int4*)(post + t0));
            int ia[TPW] = {s.x, s.y, s.z, s.w};
            int ib[TPW] = {p.x, p.y, p.z, p.w};
            int ic[TPW] = {q.x, q.y, q.z, q.w};

            // 12 independent gathers issued before first use (MLP=12).
            float4 va[TPW], vb[TPW], vc[TPW];
            #pragma unroll
            for (int j = 0; j < TPW; j++) va[j] = __ldg(W + (size_t)ia[j] * EMBED_VEC + lane);
            #pragma unroll
            for (int j = 0; j < TPW; j++) vb[j] = __ldg(W + (size_t)ib[j] * EMBED_VEC + lane);
            #pragma unroll
            for (int j = 0; j < TPW; j++) vc[j] = __ldg(W + (size_t)ic[j] * EMBED_VEC + lane);

            #pragma unroll
            for (int j = 0; j < TPW; j++) {
                float4 r;
                r.x = va[j].x + vb[j].x + vc[j].x;
                r.y = va[j].y + vb[j].y + vc[j].y;
                r.z = va[j].z + vb[j].z + vc[j].z;
                r.w = va[j].w + vb[j].w + vc[j].w;
                // Streaming store: keep the 51MB weight table L2-resident.
                __stcs(out + (size_t)(t0 + j) * EMBED_VEC + lane, r);
            }
        } else {
            for (long long t = t0; t < n_tok; t++) {
                int i0 = __ldg(seq + t), i1 = __ldg(pre + t), i2 = __ldg(post + t);
                float4 a = __ldg(W + (size_t)i0 * EMBED_VEC + lane);
                float4 b = __ldg(W + (size_t)i1 * EMBED_VEC + lane);
                float4 c = __ldg(W + (size_t)i2 * EMBED_VEC + lane);
                float4 r;
                r.x = a.x + b.x + c.x;
                r.y = a.y + b.y + c.y;
                r.z = a.z + b.z + c.z;
                r.w = a.w + b.w + c.w;
                __stcs(out + (size_t)t * EMBED_VEC + lane, r);
            }
        }
    }
}

extern "C" void kernel_launch(void* const* d_in, const int* in_sizes, int n_in,
                              void* d_out, int out_size) {
    const int*    seq  = (const int*)d_in[0];
    const int*    pre  = (const int*)d_in[1];
    const int*    post = (const int*)d_in[2];
    const float4* W    = (const float4*)d_in[3];
    float4*       out  = (float4*)d_out;

    int n_tok = in_sizes[0];  // 131072

    // Single-wave persistent grid; shrink for tiny inputs.
    int chunks = (n_tok + TPW - 1) / TPW;
    int blocks_needed = (chunks + WARPS_PER_BLOCK - 1) / WARPS_PER_BLOCK;
    int blocks = GRID_BLOCKS < blocks_needed ? GRID_BLOCKS : blocks_needed;
    if (blocks < 1) blocks = 1;

    cbow_subword_kernel<<<blocks, THREADS_PER_BLOCK>>>(seq, pre, post, W, out, n_tok);
}